// round 6
// baseline (speedup 1.0000x reference)
#include <cuda_runtime.h>
#include <cuda_bf16.h>
#include <math.h>
#include <stdint.h>

// Shapes (fixed): B*N=6400 rows, K=1024 noise, D=64, V=1e6.
#define DIM        64
#define K_NOISE    1024
#define ROWS_TOT   6400
#define MT         64                  // M tile (rows per CTA)
#define NT         128                 // N tile (noise cols per CTA)
#define A_BYTES    (MT * 128)          // 8 KB
#define B_BYTES    (NT * 128)          // 16 KB

// ---------------------------------------------------------------------------
// helpers
// ---------------------------------------------------------------------------
static __device__ __forceinline__ uint32_t smem_u32(const void* p) {
    uint32_t a;
    asm("{ .reg .u64 t; cvta.to.shared.u64 t, %1; cvt.u32.u64 %0, t; }"
        : "=r"(a) : "l"(p));
    return a;
}

static __device__ __forceinline__ void ldsm_x4(uint32_t* r, uint32_t addr) {
    asm volatile("ldmatrix.sync.aligned.m8n8.x4.shared.b16 {%0,%1,%2,%3}, [%4];"
                 : "=r"(r[0]), "=r"(r[1]), "=r"(r[2]), "=r"(r[3]) : "r"(addr));
}

static __device__ __forceinline__ void mma16816(float* d, const uint32_t* a,
                                                const uint32_t* b) {
    asm volatile(
        "mma.sync.aligned.m16n8k16.row.col.f32.bf16.bf16.f32 "
        "{%0,%1,%2,%3}, {%4,%5,%6,%7}, {%8,%9}, {%0,%1,%2,%3};"
        : "+f"(d[0]), "+f"(d[1]), "+f"(d[2]), "+f"(d[3])
        : "r"(a[0]), "r"(a[1]), "r"(a[2]), "r"(a[3]), "r"(b[0]), "r"(b[1]));
}

// softplus(x) = log(1 + e^x). Noise scores land in the polynomial branch
// (e^x ~ 1e-3) essentially always: 1 MUFU + 3 FMA on the hot path.
__device__ __forceinline__ float softplus_f(float x)
{
    if (x > 8.0f) return x + __expf(-x);
    float z = __expf(x);
    if (z < 0.015625f) return z * fmaf(z, fmaf(z, 0.33333334f, -0.5f), 1.0f);
    return __logf(1.0f + z);
}

// convert 8 consecutive f32 -> 8 bf16 packed in a uint4
static __device__ __forceinline__ uint4 cvt8_bf16(const float* src)
{
    float4 a = ((const float4*)src)[0];
    float4 b = ((const float4*)src)[1];
    __nv_bfloat162 h0 = __floats2bfloat162_rn(a.x, a.y);
    __nv_bfloat162 h1 = __floats2bfloat162_rn(a.z, a.w);
    __nv_bfloat162 h2 = __floats2bfloat162_rn(b.x, b.y);
    __nv_bfloat162 h3 = __floats2bfloat162_rn(b.z, b.w);
    uint4 p;
    p.x = *(uint32_t*)&h0; p.y = *(uint32_t*)&h1;
    p.z = *(uint32_t*)&h2; p.w = *(uint32_t*)&h3;
    return p;
}

// ---------------------------------------------------------------------------
// Tiny init kernel: zero the scalar output (stream-ordered before main).
// ---------------------------------------------------------------------------
__global__ void zero_kernel(float* __restrict__ d_out) { d_out[0] = 0.0f; }

// ---------------------------------------------------------------------------
// Fused NCE kernel: one CTA = 64 rows x 128 noise via mma.sync bf16.
//   grid = (100 M-tiles, 8 N-tiles) = 800 CTAs, 128 threads (4 warps).
//   Warp layout: warp_m = wid&1 (2 x 32 rows), warp_n = wid>>1 (2 x 64 cols),
//   each warp two 32-col passes (acc 32 regs live).
//   Target term distributed: each CTA does 8 target rows (exact f32).
// ---------------------------------------------------------------------------
__global__ void __launch_bounds__(128, 6)
nce_fused_kernel(const int* __restrict__ target,
                 const float* __restrict__ input,
                 const float* __restrict__ embs,
                 const int* __restrict__ noise_samples,
                 const float* __restrict__ logprob_noise,
                 float norm_c, float inv_rows, float* __restrict__ d_out)
{
    __shared__ __align__(1024) char s_a[A_BYTES];   // 8 KB  A (bf16 SW128)
    __shared__ __align__(1024) char s_b[B_BYTES];   // 16 KB B (bf16 SW128)
    __shared__ float s_c[NT];
    __shared__ float s_red[4];

    const int tid    = threadIdx.x;
    const int lane   = tid & 31;
    const int wid    = tid >> 5;
    const int warp_m = wid & 1;        // 2 warps over M: 32 rows each
    const int warp_n = wid >> 1;       // 2 warps over N: 64 cols each
    const int bm     = blockIdx.x;
    const int bn     = blockIdx.y;

    // --- stage A: convert 64 input rows. 512 chunks of 16B, 4 per thread ---
    // swizzle within a 128B row: chunk c at row r lands at ((c ^ (r&7)) << 4)
#pragma unroll
    for (int i = 0; i < 4; i++) {
        int flat = i * 128 + tid;            // 0..511
        int row = flat >> 3, c = flat & 7;
        uint4 p = cvt8_bf16(input + (size_t)(bm * MT + row) * DIM + c * 8);
        *(uint4*)(s_a + row * 128 + ((c ^ (row & 7)) << 4)) = p;
    }
    // --- stage B: gather + convert 128 noise rows. 1024 chunks, 8/thread ---
#pragma unroll
    for (int i = 0; i < 8; i++) {
        int flat = i * 128 + tid;            // 0..1023
        int row = flat >> 3, c = flat & 7;
        int it = noise_samples[bn * NT + row];        // L2-hot (4 KB table)
        uint4 p = cvt8_bf16(embs + (size_t)it * DIM + c * 8);
        *(uint4*)(s_b + row * 128 + ((c ^ (row & 7)) << 4)) = p;
    }
    if (tid < NT) {
        int it = noise_samples[bn * NT + tid];
        s_c[tid] = norm_c + logprob_noise[it];
    }

    // --- target term (exact f32): 8 rows per CTA, evenly distributed ---
    float local = 0.0f;
    if (tid < 8) {
        int r = bm * MT + bn * 8 + tid;
        int t = target[r];
        const float4* ti = (const float4*)(input + (size_t)r * DIM);
        const float4* te = (const float4*)(embs + (size_t)t * DIM);
        float acc = 0.0f;
#pragma unroll
        for (int i = 0; i < DIM / 4; i++) {
            float4 x = ti[i], e = te[i];
            acc = fmaf(x.x, e.x, fmaf(x.y, e.y, fmaf(x.z, e.z, fmaf(x.w, e.w, acc))));
        }
        float xt = acc - norm_c - logprob_noise[t];
        local += softplus_f(-xt);
    }
    __syncthreads();

    const uint32_t a_base = smem_u32(s_a);
    const uint32_t b_base = smem_u32(s_b);

    // --- two 32-col passes per warp ---
#pragma unroll
    for (int np = 0; np < 2; np++) {
        float acc[2][4][4] = {};
#pragma unroll
        for (int k = 0; k < 4; k++) {           // K = 4 x k16
            uint32_t afr[2][4];
#pragma unroll
            for (int mi = 0; mi < 2; mi++) {
                uint32_t row   = warp_m * 32 + mi * 16 + (lane & 15);
                uint32_t chunk = k * 2 + (lane >> 4);
                ldsm_x4(afr[mi], a_base + row * 128 + ((chunk ^ (row & 7)) << 4));
            }
            uint32_t bfr[4][2];
#pragma unroll
            for (int nj = 0; nj < 2; nj++) {
                uint32_t row = warp_n * 64 + np * 32 + nj * 16
                             + (lane & 7) + ((lane >> 4) << 3);
                uint32_t chunk = k * 2 + ((lane >> 3) & 1);
                uint32_t b4[4];
                ldsm_x4(b4, b_base + row * 128 + ((chunk ^ (row & 7)) << 4));
                bfr[nj * 2][0]     = b4[0]; bfr[nj * 2][1]     = b4[1];
                bfr[nj * 2 + 1][0] = b4[2]; bfr[nj * 2 + 1][1] = b4[3];
            }
#pragma unroll
            for (int mi = 0; mi < 2; mi++)
#pragma unroll
                for (int ni = 0; ni < 4; ni++)
                    mma16816(acc[mi][ni], afr[mi], bfr[ni]);
        }
        // epilogue for this 32-col pass
#pragma unroll
        for (int ni = 0; ni < 4; ni++) {
            int col = warp_n * 64 + np * 32 + ni * 8 + (lane & 3) * 2;
            float c0 = s_c[col], c1 = s_c[col + 1];
#pragma unroll
            for (int mi = 0; mi < 2; mi++) {
                local += softplus_f(acc[mi][ni][0] - c0);
                local += softplus_f(acc[mi][ni][1] - c1);
                local += softplus_f(acc[mi][ni][2] - c0);
                local += softplus_f(acc[mi][ni][3] - c1);
            }
        }
    }

    // --- reduce block, one atomicAdd ---
#pragma unroll
    for (int o = 16; o; o >>= 1)
        local += __shfl_xor_sync(0xffffffffu, local, o);
    if (lane == 0) s_red[wid] = local;
    __syncthreads();
    if (tid == 0)
        atomicAdd(d_out, (s_red[0] + s_red[1] + s_red[2] + s_red[3]) * inv_rows);
}

// ---------------------------------------------------------------------------
// Launch. Inputs (metadata order): target i32[6400], input f32[6400*64],
// embs f32[1e6*64], noise_samples i32[1024], logprob_noise f32[1e6].
// Output: f32[1] (mean loss).
// ---------------------------------------------------------------------------
extern "C" void kernel_launch(void* const* d_in, const int* in_sizes, int n_in,
                              void* d_out, int out_size)
{
    const int*   target = (const int*)d_in[0];
    const float* input  = (const float*)d_in[1];
    const float* embs   = (const float*)d_in[2];
    const int*   noise  = (const int*)d_in[3];
    const float* lpn    = (const float*)d_in[4];
    float*       out    = (float*)d_out;

    const int rows = in_sizes[0];                              // 6400
    const float norm_c = logf((float)in_sizes[4]) + logf((float)in_sizes[3]);

    zero_kernel<<<1, 1>>>(out);
    dim3 grid(ROWS_TOT / MT, K_NOISE / NT);                    // 100 x 8
    nce_fused_kernel<<<grid, 128>>>(target, input, embs, noise, lpn,
                                    norm_c, 1.0f / (float)rows, out);
}